// round 1
// baseline (speedup 1.0000x reference)
#include <cuda_runtime.h>

#define N_   128
#define C_   64
#define CO_  64
#define T_   256
#define V_   25
#define R_   8
#define TT_  16
#define ADJP 28   // padded adj row (floats) for aligned float4 loads

// scratch (device globals -- no allocation allowed)
__device__ float g_xm[N_ * C_ * V_];            // [n][c][v]  t-sums
__device__ float g_adj[N_ * CO_ * V_ * ADJP];   // [n][o][u][28]

typedef unsigned long long u64;

__device__ __forceinline__ u64 pack2(float lo, float hi) {
    u64 r; asm("mov.b64 %0, {%1,%2};" : "=l"(r) : "f"(lo), "f"(hi)); return r;
}
__device__ __forceinline__ void unpack2(u64 v, float& lo, float& hi) {
    asm("mov.b64 {%0,%1}, %2;" : "=f"(lo), "=f"(hi) : "l"(v));
}
__device__ __forceinline__ u64 fma2(u64 a, u64 b, u64 c) {
    u64 d; asm("fma.rn.f32x2 %0, %1, %2, %3;" : "=l"(d) : "l"(a), "l"(b), "l"(c)); return d;
}

// ---------------------------------------------------------------------------
// Kernel 1: xm[n,c,v] = sum_t x[n,c,t,v]   (one coalesced pass over x)
// grid = N*C blocks, 256 threads
// ---------------------------------------------------------------------------
__global__ void k1_tsum(const float* __restrict__ x) {
    __shared__ float tile[T_ * V_];           // 6400 floats
    __shared__ float part[8][V_];
    const int bx  = blockIdx.x;               // n*64 + c
    const int tid = threadIdx.x;

    const float4* src = reinterpret_cast<const float4*>(x + (size_t)bx * (T_ * V_));
    float4* dst = reinterpret_cast<float4*>(tile);
    for (int i = tid; i < (T_ * V_) / 4; i += 256) dst[i] = src[i];
    __syncthreads();

    if (tid < 200) {
        const int g = tid / 25, v = tid - g * 25;
        float s = 0.f;
        const int tb = g * 32;
        #pragma unroll 8
        for (int t = tb; t < tb + 32; ++t) s += tile[t * V_ + v];
        part[g][v] = s;
    }
    __syncthreads();

    if (tid < V_) {
        float s = 0.f;
        #pragma unroll
        for (int g = 0; g < 8; ++g) s += part[g][tid];
        g_xm[bx * V_ + tid] = s;
    }
}

// ---------------------------------------------------------------------------
// Kernel 2: adj[n,o,u,v] = sum_r W4[o,r]*tanh(x1[n,r,u]-x2[n,r,v]) + b4[o] + A[u,v]
// x1/x2 = W{1,2} @ xm / T + b{1,2}.   grid = N blocks, 256 threads
// ---------------------------------------------------------------------------
__global__ void k2_adj(const float* __restrict__ A,
                       const float* __restrict__ W1, const float* __restrict__ b1,
                       const float* __restrict__ W2, const float* __restrict__ b2,
                       const float* __restrict__ W4, const float* __restrict__ b4) {
    __shared__ float sxm[C_ * V_];   // 1600
    __shared__ float sx1[R_ * V_];   // 200
    __shared__ float sx2[R_ * V_];
    __shared__ float sW4[CO_ * R_];  // 512
    __shared__ float sA[V_ * V_];    // 625
    __shared__ float sb4[CO_];

    const int n = blockIdx.x, tid = threadIdx.x;
    for (int i = tid; i < C_ * V_;  i += 256) sxm[i] = g_xm[n * C_ * V_ + i];
    for (int i = tid; i < CO_ * R_; i += 256) sW4[i] = W4[i];
    for (int i = tid; i < V_ * V_;  i += 256) sA[i]  = A[i];
    if (tid < CO_) sb4[tid] = b4[tid];
    __syncthreads();

    if (tid < R_ * V_) {
        const int r = tid / V_, v = tid - r * V_;
        float s1 = 0.f, s2 = 0.f;
        for (int c = 0; c < C_; ++c) {
            const float xv = sxm[c * V_ + v];
            s1 = fmaf(W1[r * C_ + c], xv, s1);
            s2 = fmaf(W2[r * C_ + c], xv, s2);
        }
        sx1[tid] = s1 * (1.0f / T_) + b1[r];
        sx2[tid] = s2 * (1.0f / T_) + b2[r];
    }
    __syncthreads();

    for (int p = tid; p < V_ * V_; p += 256) {
        const int u = p / V_, v = p - u * V_;
        float y[R_];
        #pragma unroll
        for (int r = 0; r < R_; ++r) y[r] = tanhf(sx1[r * V_ + u] - sx2[r * V_ + v]);
        const float av = sA[p];
        float* out = &g_adj[((size_t)(n * CO_) * V_ + u) * ADJP + v];
        for (int o = 0; o < CO_; ++o) {
            float s = sb4[o];
            #pragma unroll
            for (int r = 0; r < R_; ++r) s = fmaf(sW4[o * R_ + r], y[r], s);
            out[(size_t)o * V_ * ADJP] = s + av;
        }
    }
}

// ---------------------------------------------------------------------------
// Kernel 3 (main): per block = (n, 16-timestep tile)
//   stage1: x3[o,t,v] = b3[o] + sum_c W3[o,c] x[n,c,t,v]  (f32x2 packed FMA)
//   stage2: z[o,t,u]  = sum_v adj[n,o,u,v] x3[o,t,v]      (adj rows in regs)
// smem: sx [64][16][26] + sx3 [64][401] + sW3t [64][64] = 225,536 B
// ---------------------------------------------------------------------------
__global__ void __launch_bounds__(256, 1)
k3_main(const float* __restrict__ x, const float* __restrict__ W3,
        const float* __restrict__ b3, float* __restrict__ z) {
    extern __shared__ float sm[];
    float* sx   = sm;                       // 64*16*26 = 26624 floats
    float* sx3  = sm + 26624;               // 64*401   = 25664 floats
    float* sW3t = sm + 26624 + 25664;       // 64*64    = 4096 floats

    const int bx  = blockIdx.x;
    const int n   = bx >> 4;
    const int t0  = (bx & 15) * TT_;
    const int tid = threadIdx.x;

    // W3 transposed into smem: sW3t[c][o]
    for (int i = tid; i < C_ * CO_; i += 256) {
        const int c = i >> 6, o = i & 63;
        sW3t[i] = W3[o * C_ + c];
    }
    // x tile: [c][t][26pad]
    const float* xg = x + ((size_t)n * C_ * T_ + t0) * V_;
    for (int q = tid; q < 64 * 100; q += 256) {
        const int c = q / 100, j = q - c * 100;
        const float4 val = *reinterpret_cast<const float4*>(xg + (size_t)c * (T_ * V_) + j * 4);
        const int e = j * 4;
        float fv[4] = {val.x, val.y, val.z, val.w};
        #pragma unroll
        for (int k = 0; k < 4; ++k) {
            const int ee = e + k;
            const int t = ee / 25, v = ee - t * 25;
            sx[c * (TT_ * 26) + t * 26 + v] = fv[k];
        }
    }
    __syncthreads();

    // ---- stage 1: thread = (o-quad, t); warp covers 2 t's (x-row broadcast) ----
    {
        const int t  = tid >> 4;
        const int o0 = (tid & 15) * 4;
        u64 acc[4][13];
        #pragma unroll
        for (int i = 0; i < 4; ++i) {
            const float b = b3[o0 + i];
            #pragma unroll
            for (int j = 0; j < 13; ++j) acc[i][j] = pack2(b, b);
        }
        #pragma unroll 4
        for (int c = 0; c < C_; ++c) {
            const float4 wq = *reinterpret_cast<const float4*>(&sW3t[c * 64 + o0]);
            u64 w2[4] = {pack2(wq.x, wq.x), pack2(wq.y, wq.y),
                         pack2(wq.z, wq.z), pack2(wq.w, wq.w)};
            const u64* xr = reinterpret_cast<const u64*>(&sx[c * (TT_ * 26) + t * 26]);
            u64 xv[13];
            #pragma unroll
            for (int j = 0; j < 13; ++j) xv[j] = xr[j];
            #pragma unroll
            for (int i = 0; i < 4; ++i)
                #pragma unroll
                for (int j = 0; j < 13; ++j)
                    acc[i][j] = fma2(xv[j], w2[i], acc[i][j]);
        }
        #pragma unroll
        for (int i = 0; i < 4; ++i) {
            float* dst = &sx3[(o0 + i) * 401 + t * 25];
            #pragma unroll
            for (int j = 0; j < 12; ++j) {
                float lo, hi; unpack2(acc[i][j], lo, hi);
                dst[2 * j] = lo; dst[2 * j + 1] = hi;
            }
            float lo, hi; unpack2(acc[i][12], lo, hi);
            dst[24] = lo;   // v=24 (upper lane is pad)
        }
    }
    __syncthreads();

    // ---- stage 2: thread = (o, u-stripe ug); u = ug + 4k ----
    {
        const int o  = tid >> 2;
        const int ug = tid & 3;
        const int ktot = (ug == 0) ? 7 : 6;                 // 25 = 7+6+6+6
        const float* arow_base = &g_adj[(size_t)(n * CO_ + o) * V_ * ADJP];
        float* zbase = z + ((size_t)(n * CO_ + o) * T_ + t0) * V_;
        const float* x3row = &sx3[o * 401];

        #pragma unroll
        for (int half = 0; half < 2; ++half) {
            const int k0 = half ? 3 : 0;
            const int nr = half ? (ktot - 3) : 3;           // 3 or (3|4)
            float ar[4][25];
            #pragma unroll
            for (int kk = 0; kk < 4; ++kk) {
                if (kk < nr) {
                    const float* row = arow_base + (ug + 4 * (k0 + kk)) * ADJP;
                    #pragma unroll
                    for (int j = 0; j < 6; ++j) {
                        const float4 f = *reinterpret_cast<const float4*>(row + j * 4);
                        ar[kk][4 * j + 0] = f.x; ar[kk][4 * j + 1] = f.y;
                        ar[kk][4 * j + 2] = f.z; ar[kk][4 * j + 3] = f.w;
                    }
                    ar[kk][24] = row[24];
                }
            }
            #pragma unroll 2
            for (int t = 0; t < TT_; ++t) {
                float xv[25];
                #pragma unroll
                for (int v = 0; v < 25; ++v) xv[v] = x3row[t * 25 + v];
                float* zrow = zbase + t * V_;
                #pragma unroll
                for (int kk = 0; kk < 4; ++kk) {
                    if (kk < nr) {
                        float s = 0.f;
                        #pragma unroll
                        for (int v = 0; v < 25; ++v) s = fmaf(ar[kk][v], xv[v], s);
                        zrow[ug + 4 * (k0 + kk)] = s;
                    }
                }
            }
        }
    }
}

// ---------------------------------------------------------------------------
extern "C" void kernel_launch(void* const* d_in, const int* in_sizes, int n_in,
                              void* d_out, int out_size) {
    (void)in_sizes; (void)n_in; (void)out_size;
    const float* x  = (const float*)d_in[0];
    const float* A  = (const float*)d_in[1];
    const float* W1 = (const float*)d_in[2];
    const float* b1 = (const float*)d_in[3];
    const float* W2 = (const float*)d_in[4];
    const float* b2 = (const float*)d_in[5];
    const float* W3 = (const float*)d_in[6];
    const float* b3 = (const float*)d_in[7];
    const float* W4 = (const float*)d_in[8];
    const float* b4 = (const float*)d_in[9];
    float* z = (float*)d_out;

    cudaFuncSetAttribute(k3_main, cudaFuncAttributeMaxDynamicSharedMemorySize, 225536);

    k1_tsum<<<N_ * C_, 256>>>(x);
    k2_adj<<<N_, 256>>>(A, W1, b1, W2, b2, W4, b4);
    k3_main<<<N_ * 16, 256, 225536>>>(x, W3, b3, z);
}